// round 9
// baseline (speedup 1.0000x reference)
#include <cuda_runtime.h>
#include <cstdint>

// Haar DWT2 on x:[8,64,512,512] f32 -> 4 subbands [8,64,256,256] packed
// subband-major into d_out (LL, LH, HL, HH).
//
// Round 8: best config (BLOCK=1024, 154.1us, DRAM 86.6%) + the one remaining
// unconfounded variable: streaming stores (__stcs). Output is write-once /
// never-read; evict-first policy lets L2 retire dirty lines sooner without
// displacing in-flight read sectors. Loads stay plain __ldg (streaming loads
// showed no benefit in R2).
//
// Each thread: 2 output columns of one output row.
//   reads  float4 from input rows 2i and 2i+1  (32 B)
//   writes float2 to each of 4 subbands        (32 B, __stcs)

static constexpr int W_IN = 512;
static constexpr int H_OUT = 256;
static constexpr int W_OUT = 256;
static constexpr int PAIRS_PER_ROW = W_OUT / 2;                  // 128 threads per output row
static constexpr long long PLANE_IN  = (long long)W_IN * W_IN;   // 262144
static constexpr long long PLANE_OUT = (long long)H_OUT * W_OUT; // 65536
static constexpr long long SUBBAND_STRIDE = 512LL * PLANE_OUT;   // 33,554,432

static constexpr unsigned BLOCK = 1024;

__global__ void __launch_bounds__(BLOCK)
haar_dwt2_kernel(const float* __restrict__ x, float* __restrict__ out)
{
    const unsigned tid = blockIdx.x * BLOCK + threadIdx.x;
    // tid layout: [plane p : 512][out-row i : 256][col-pair j2 : 128]
    const unsigned j2 = tid & (PAIRS_PER_ROW - 1);       // 0..127
    const unsigned i  = (tid >> 7) & (H_OUT - 1);        // 0..255
    const unsigned p  = tid >> 15;                       // 0..511

    const float* base = x + (long long)p * PLANE_IN + (long long)(2u * i) * W_IN;
    const float4 r0 = __ldg((const float4*)base + j2);              // row 2i
    const float4 r1 = __ldg((const float4*)base + (W_IN / 4) + j2); // row 2i+1

    const float s = 0.5f;

    float2 ll, lh, hl, hh;
    {
        const float apb = r0.x + r0.y, amb = r0.x - r0.y;
        const float cpd = r1.x + r1.y, cmd = r1.x - r1.y;
        ll.x = (apb + cpd) * s;
        lh.x = (apb - cpd) * s;
        hl.x = (amb + cmd) * s;
        hh.x = (amb - cmd) * s;
    }
    {
        const float apb = r0.z + r0.w, amb = r0.z - r0.w;
        const float cpd = r1.z + r1.w, cmd = r1.z - r1.w;
        ll.y = (apb + cpd) * s;
        lh.y = (apb - cpd) * s;
        hl.y = (amb + cmd) * s;
        hh.y = (amb - cmd) * s;
    }

    const long long obase = (long long)p * PLANE_OUT + (long long)i * W_OUT + 2u * j2;
    __stcs((float2*)(out + obase),                      ll);
    __stcs((float2*)(out + obase +     SUBBAND_STRIDE), lh);
    __stcs((float2*)(out + obase + 2 * SUBBAND_STRIDE), hl);
    __stcs((float2*)(out + obase + 3 * SUBBAND_STRIDE), hh);
}

extern "C" void kernel_launch(void* const* d_in, const int* in_sizes, int n_in,
                              void* d_out, int out_size)
{
    const float* x = (const float*)d_in[0];
    float* out = (float*)d_out;

    // total threads = 512 planes * 256 rows * 128 pairs = 16,777,216
    const unsigned total = 512u * 256u * 128u;
    const unsigned grid = total / BLOCK; // 16384
    haar_dwt2_kernel<<<grid, BLOCK>>>(x, out);
}

// round 10
// speedup vs baseline: 1.0085x; 1.0085x over previous
#include <cuda_runtime.h>
#include <cstdint>

// Haar DWT2 on x:[8,64,512,512] f32 -> 4 subbands [8,64,256,256] packed
// subband-major into d_out (LL, LH, HL, HH).
//
// FINAL (R7 config, re-confirmed): BLOCK=1024, plain __ldg float4 loads,
// plain float2 stores. Measured 154.1us, DRAM=86.6%, HBM=6860 GB/s (85.8%
// of spec) — the mixed 1:1 read/write HBM3e ceiling on this part. Exhausted
// axes (all neutral or worse): access width (R2), ldcs/stcs cache policy
// (R2/R8), persistent grid + prefetch pipelining (R3), CTA granularity
// 256/512/1024 (R1/R6/R7 — 1024 best by ~1.3% via per-CTA 128 KiB
// contiguous read footprint / DRAM row-buffer locality).
//
// Each thread: 2 output columns of one output row.
//   reads  float4 from input rows 2i and 2i+1  (32 B)
//   writes float2 to each of 4 subbands        (32 B)

static constexpr int W_IN = 512;
static constexpr int H_OUT = 256;
static constexpr int W_OUT = 256;
static constexpr int PAIRS_PER_ROW = W_OUT / 2;                  // 128 threads per output row
static constexpr long long PLANE_IN  = (long long)W_IN * W_IN;   // 262144
static constexpr long long PLANE_OUT = (long long)H_OUT * W_OUT; // 65536
static constexpr long long SUBBAND_STRIDE = 512LL * PLANE_OUT;   // 33,554,432

static constexpr unsigned BLOCK = 1024;

__global__ void __launch_bounds__(BLOCK)
haar_dwt2_kernel(const float* __restrict__ x, float* __restrict__ out)
{
    const unsigned tid = blockIdx.x * BLOCK + threadIdx.x;
    // tid layout: [plane p : 512][out-row i : 256][col-pair j2 : 128]
    const unsigned j2 = tid & (PAIRS_PER_ROW - 1);       // 0..127
    const unsigned i  = (tid >> 7) & (H_OUT - 1);        // 0..255
    const unsigned p  = tid >> 15;                       // 0..511

    const float* base = x + (long long)p * PLANE_IN + (long long)(2u * i) * W_IN;
    const float4 r0 = __ldg((const float4*)base + j2);              // row 2i
    const float4 r1 = __ldg((const float4*)base + (W_IN / 4) + j2); // row 2i+1

    const float s = 0.5f;

    float2 ll, lh, hl, hh;
    {
        const float apb = r0.x + r0.y, amb = r0.x - r0.y;
        const float cpd = r1.x + r1.y, cmd = r1.x - r1.y;
        ll.x = (apb + cpd) * s;
        lh.x = (apb - cpd) * s;
        hl.x = (amb + cmd) * s;
        hh.x = (amb - cmd) * s;
    }
    {
        const float apb = r0.z + r0.w, amb = r0.z - r0.w;
        const float cpd = r1.z + r1.w, cmd = r1.z - r1.w;
        ll.y = (apb + cpd) * s;
        lh.y = (apb - cpd) * s;
        hl.y = (amb + cmd) * s;
        hh.y = (amb - cmd) * s;
    }

    const long long obase = (long long)p * PLANE_OUT + (long long)i * W_OUT + 2u * j2;
    *(float2*)(out + obase)                      = ll;
    *(float2*)(out + obase +     SUBBAND_STRIDE) = lh;
    *(float2*)(out + obase + 2 * SUBBAND_STRIDE) = hl;
    *(float2*)(out + obase + 3 * SUBBAND_STRIDE) = hh;
}

extern "C" void kernel_launch(void* const* d_in, const int* in_sizes, int n_in,
                              void* d_out, int out_size)
{
    const float* x = (const float*)d_in[0];
    float* out = (float*)d_out;

    // total threads = 512 planes * 256 rows * 128 pairs = 16,777,216
    const unsigned total = 512u * 256u * 128u;
    const unsigned grid = total / BLOCK; // 16384
    haar_dwt2_kernel<<<grid, BLOCK>>>(x, out);
}